// round 12
// baseline (speedup 1.0000x reference)
#include <cuda_runtime.h>
#include <cuda_bf16.h>
#include <cuda_fp16.h>
#include <math.h>

#define BATCH 32
#define NTOK  4096
#define DIM   256
#define M_TOT 672
#define MPAD  768

// ---------------- scratch ----------------
__device__ __half g_Qh[MPAD * DIM];          // Q' * 64
__device__ float  g_c [MPAD];
__device__ __half g_E [(long)BATCH * MPAD * NTOK];
__device__ __half g_Xh[(long)BATCH * NTOK * DIM];
__device__ __half g_Xl[(long)BATCH * NTOK * DIM];
__device__ float g_rs[BATCH * MPAD];
__device__ float g_H0[(long)BATCH * MPAD * DIM];
__device__ float g_H1[(long)BATCH * MPAD * DIM];
__device__ float g_sw[BATCH * M_TOT];
__device__ float g_part[BATCH * 16 * DIM];
__device__ float g_cnt [BATCH * 16];

// ---------------- helpers ----------------
__device__ __forceinline__ unsigned sm_u32(const void* p) {
    return (unsigned)__cvta_generic_to_shared(p);
}
__device__ __forceinline__ void cpa16(unsigned s, const void* g) {
    asm volatile("cp.async.cg.shared.global [%0], [%1], 16;" :: "r"(s), "l"(g));
}
__device__ __forceinline__ void cpa_commit() { asm volatile("cp.async.commit_group;"); }
template<int N> __device__ __forceinline__ void cpa_wait() {
    asm volatile("cp.async.wait_group %0;" :: "n"(N));
}
__device__ __forceinline__ void ldsm4(unsigned r[4], unsigned addr) {
    asm volatile("ldmatrix.sync.aligned.m8n8.x4.shared.b16 {%0,%1,%2,%3},[%4];"
                 : "=r"(r[0]), "=r"(r[1]), "=r"(r[2]), "=r"(r[3]) : "r"(addr));
}
__device__ __forceinline__ void ldsm2(unsigned r[2], unsigned addr) {
    asm volatile("ldmatrix.sync.aligned.m8n8.x2.shared.b16 {%0,%1},[%2];"
                 : "=r"(r[0]), "=r"(r[1]) : "r"(addr));
}
__device__ __forceinline__ void ldsm2t(unsigned r[2], unsigned addr) {
    asm volatile("ldmatrix.sync.aligned.m8n8.x2.trans.shared.b16 {%0,%1},[%2];"
                 : "=r"(r[0]), "=r"(r[1]) : "r"(addr));
}
__device__ __forceinline__ void mma16816(float c[4], const unsigned a[4], const unsigned b[2]) {
    asm volatile(
        "mma.sync.aligned.m16n8k16.row.col.f32.f16.f16.f32 "
        "{%0,%1,%2,%3},{%4,%5,%6,%7},{%8,%9},{%0,%1,%2,%3};"
        : "+f"(c[0]), "+f"(c[1]), "+f"(c[2]), "+f"(c[3])
        : "r"(a[0]), "r"(a[1]), "r"(a[2]), "r"(a[3]), "r"(b[0]), "r"(b[1]));
}

// ---------------- zero rowsums ----------------
__global__ __launch_bounds__(256)
void rs_zero(float* __restrict__ rs)
{
    rs[blockIdx.x * 256 + threadIdx.x] = 0.f;
}

// ---------------- X -> fp16 hi/lo ----------------
__global__ __launch_bounds__(256)
void convert_x(const float4* __restrict__ X, __half2* __restrict__ Xh,
               __half2* __restrict__ Xl)
{
    long i = (long)blockIdx.x * 256 + threadIdx.x;
    float4 v = X[i];
    __half hx = __float2half(v.x), hy = __float2half(v.y);
    __half hz = __float2half(v.z), hw = __float2half(v.w);
    Xh[i * 2]     = __halves2half2(hx, hy);
    Xh[i * 2 + 1] = __halves2half2(hz, hw);
    Xl[i * 2]     = __halves2half2(__float2half(v.x - __half2float(hx)),
                                   __float2half(v.y - __half2float(hy)));
    Xl[i * 2 + 1] = __halves2half2(__float2half(v.z - __half2float(hz)),
                                   __float2half(v.w - __half2float(hw)));
}

// ---------------- prep ----------------
__global__ __launch_bounds__(256)
void prep_q(const float* __restrict__ cat, const float* __restrict__ typ,
            const float* __restrict__ var, const float* __restrict__ sp,
            const float* __restrict__ Wcat, const float* __restrict__ bcat,
            const float* __restrict__ Wtype, const float* __restrict__ btype,
            const float* __restrict__ Wvar, const float* __restrict__ bvar,
            const float* __restrict__ Wsp, const float* __restrict__ bsp,
            const float* __restrict__ Wk, const float* __restrict__ bk,
            __half* __restrict__ Qh, float* __restrict__ cvec)
{
    int m = blockIdx.x;
    const float* codes; const float* Wq; const float* bq;
    if (m < 16)       { codes = cat + m * DIM;         Wq = Wcat;  bq = bcat; }
    else if (m < 144) { codes = typ + (m - 16) * DIM;  Wq = Wtype; bq = btype; }
    else if (m < 656) { codes = var + (m - 144) * DIM; Wq = Wvar;  bq = bvar; }
    else              { codes = sp + (m - 656) * DIM;  Wq = Wsp;   bq = bsp; }

    __shared__ float cs[DIM], qs[DIM], red[256];
    int t = threadIdx.x;
    cs[t] = codes[t];
    __syncthreads();

    int w = t >> 5, l = t & 31;
    for (int j = w; j < DIM; j += 8) {
        const float* wr = Wq + j * DIM;
        float s = 0.f;
        #pragma unroll
        for (int i = 0; i < 8; i++) s += wr[l + 32 * i] * cs[l + 32 * i];
        #pragma unroll
        for (int o = 16; o > 0; o >>= 1) s += __shfl_xor_sync(0xffffffffu, s, o);
        if (l == 0) qs[j] = s + bq[j];
    }
    __syncthreads();

    float a = 0.f;
    for (int j = 0; j < DIM; j++) a += qs[j] * Wk[j * DIM + t];
    Qh[m * DIM + t] = __float2half(a * 64.0f);

    red[t] = qs[t] * bk[t];
    __syncthreads();
    for (int s = 128; s > 0; s >>= 1) { if (t < s) red[t] += red[t + s]; __syncthreads(); }
    if (t == 0) cvec[m] = red[0] * 0.0625f;
}

// ---------------- logits+exp (3-stage pipeline) ----------------
extern __shared__ char dsm[];

__global__ __launch_bounds__(256)
void logits_mma(const __half* __restrict__ Qh,
                const __half* __restrict__ Xh,
                __half* __restrict__ E,
                float* __restrict__ rowsum,
                const float* __restrict__ cvec,
                const unsigned char* __restrict__ mask)
{
    const int SK = 40;
    const int STAGE = 20480;
    const int SE = 136;

    int b = blockIdx.z;
    int m0 = blockIdx.y * 128, n0 = blockIdx.x * 128;
    const __half* Xb = Xh + (long)b * NTOK * DIM;
    int t = threadIdx.x, lane = t & 31, w = t >> 5;
    int wm = (w >> 2) * 64, wn = (w & 3) * 32;
    int l15 = lane & 15, t4 = lane & 3;

    unsigned char* maskc = (unsigned char*)(dsm + 3 * STAGE);
    if (t < 128) maskc[t] = mask[(long)b * NTOK + n0 + t];

    auto load_stage = [&](int kt, int s) {
        char* base = dsm + s * STAGE;
        #pragma unroll
        for (int i = 0; i < 2; i++) {
            int c = t + i * 256;
            int row = c >> 2, kq = c & 3;
            cpa16(sm_u32(base + (row * SK + kq * 8) * 2),
                  Qh + (m0 + row) * DIM + kt * 32 + kq * 8);
            cpa16(sm_u32(base + 10240 + (row * SK + kq * 8) * 2),
                  Xb + (long)(n0 + row) * DIM + kt * 32 + kq * 8);
        }
        cpa_commit();
    };

    float acc[4][4][4] = {};
    load_stage(0, 0);
    load_stage(1, 1);
    for (int kt = 0; kt < 8; kt++) {
        cpa_wait<1>();
        __syncthreads();
        if (kt + 2 < 8) load_stage(kt + 2, (kt + 2) % 3);
        char* base = dsm + (kt % 3) * STAGE;
        unsigned aBase = sm_u32(base + ((wm + l15) * SK + (lane >> 4) * 8) * 2);
        unsigned bBase = sm_u32(base + 10240 + ((wn + (l15 & 7)) * SK + (l15 >> 3) * 8) * 2);
        #pragma unroll
        for (int ks = 0; ks < 2; ks++) {
            unsigned a[4][4], bf[4][2];
            #pragma unroll
            for (int mi = 0; mi < 4; mi++) ldsm4(a[mi], aBase + (unsigned)(mi * 16 * SK + ks * 16) * 2u);
            #pragma unroll
            for (int ni = 0; ni < 4; ni++) ldsm2(bf[ni], bBase + (unsigned)(ni * 8 * SK + ks * 16) * 2u);
            #pragma unroll
            for (int mi = 0; mi < 4; mi++)
                #pragma unroll
                for (int ni = 0; ni < 4; ni++) mma16816(acc[mi][ni], a[mi], bf[ni]);
        }
    }
    cpa_wait<0>();
    __syncthreads();   // reuse stage smem for epilogue staging

    __half* sE = (__half*)dsm;
    const float DS = 1.0f / 1024.0f;

    #pragma unroll
    for (int mi = 0; mi < 4; mi++) {
        #pragma unroll
        for (int r = 0; r < 2; r++) {
            int row = wm + mi * 16 + (lane >> 2) + r * 8;
            float cv = cvec[m0 + row];
            float rs = 0.f;
            #pragma unroll
            for (int ni = 0; ni < 4; ni++) {
                int col = wn + ni * 8 + t4 * 2;
                float x0 = acc[mi][ni][r * 2 + 0] * DS + cv;
                float x1 = acc[mi][ni][r * 2 + 1] * DS + cv;
                x0 = fminf(fmaxf(x0, -50.f), 50.f);
                x1 = fminf(fmaxf(x1, -50.f), 50.f);
                if (!maskc[col])     x0 = -50.f;
                if (!maskc[col + 1]) x1 = -50.f;
                float e0 = __expf(x0);
                float e1 = __expf(x1);
                rs += e0 + e1;
                *(__half2*)(sE + row * SE + col) =
                    __halves2half2(__float2half(e0), __float2half(e1));
            }
            rs += __shfl_xor_sync(0xffffffffu, rs, 1);
            rs += __shfl_xor_sync(0xffffffffu, rs, 2);
            if (t4 == 0) atomicAdd(&rowsum[b * MPAD + m0 + row], rs);
        }
    }
    __syncthreads();

    long robase = ((long)b * MPAD + m0) * NTOK + n0;
    #pragma unroll
    for (int i = 0; i < 8; i++) {
        int c = t + i * 256;
        int row = c >> 4, seg = c & 15;
        uint4 vh = *(uint4*)(sE + row * SE + seg * 8);
        *(uint4*)(E + robase + (long)row * NTOK + seg * 8) = vh;
    }
}

// ---------------- H partials: Hp = (E @ X) / rowsum over a K split ----------------
__global__ __launch_bounds__(256)
void h_mma(const __half* __restrict__ E,
           const __half* __restrict__ Xh, const __half* __restrict__ Xl,
           const float* __restrict__ rowsum,
           float* __restrict__ H0, float* __restrict__ H1)
{
    const int SK = 40, SN = 264;
    const int STAGE = 38912;

    int b = blockIdx.z;
    int split = blockIdx.x;              // 0 or 1
    int k0 = split * 64;                 // of 128 K-chunks
    int m0 = blockIdx.y * 64;
    float* Hp = split ? H1 : H0;
    const __half* Eb  = E  + ((long)b * MPAD + m0) * NTOK;
    const __half* Xhb = Xh + (long)b * NTOK * DIM;
    const __half* Xlb = Xl + (long)b * NTOK * DIM;
    int t = threadIdx.x, lane = t & 31, w = t >> 5;
    int wm = (w >> 2) * 32, wd = (w & 3) * 64;
    int l15 = lane & 15;

    auto load_stage = [&](int kt, int s) {
        char* base = dsm + s * STAGE;
        {
            int row = t >> 2, kq = t & 3;
            long off = (long)row * NTOK + kt * 32 + kq * 8;
            cpa16(sm_u32(base + (row * SK + kq * 8) * 2), Eb + off);
        }
        #pragma unroll
        for (int i = 0; i < 4; i++) {
            int c = t + i * 256;
            int kr = c >> 5, nc = (c & 31) * 8;
            long off = (long)(kt * 32 + kr) * DIM + nc;
            cpa16(sm_u32(base + 5120 + (kr * SN + nc) * 2), Xhb + off);
            cpa16(sm_u32(base + 22016 + (kr * SN + nc) * 2), Xlb + off);
        }
        cpa_commit();
    };

    float acc[2][8][4] = {};
    load_stage(k0, 0);
    for (int i = 0; i < 64; i++) {
        int kt = k0 + i;
        cpa_wait<0>();
        __syncthreads();
        if (i < 63) load_stage(kt + 1, (i + 1) & 1);
        char* base = dsm + (i & 1) * STAGE;
        unsigned aB  = sm_u32(base + ((wm + l15) * SK + (lane >> 4) * 8) * 2);
        unsigned bhB = sm_u32(base + 5120 + (l15 * SN + wd) * 2);
        unsigned blB = bhB + (22016 - 5120);
        #pragma unroll
        for (int ks = 0; ks < 2; ks++) {
            unsigned a[2][4];
            ldsm4(a[0], aB + (unsigned)(0 * 16 * SK + ks * 16) * 2u);
            ldsm4(a[1], aB + (unsigned)(1 * 16 * SK + ks * 16) * 2u);
            #pragma unroll
            for (int nj = 0; nj < 8; nj++) {
                unsigned bh[2], bl[2];
                ldsm2t(bh, bhB + (unsigned)(ks * 16 * SN) * 2u + (unsigned)nj * 16u);
                ldsm2t(bl, blB + (unsigned)(ks * 16 * SN) * 2u + (unsigned)nj * 16u);
                mma16816(acc[0][nj], a[0], bh);
                mma16816(acc[1][nj], a[1], bh);
                mma16816(acc[0][nj], a[0], bl);
                mma16816(acc[1][nj], a[1], bl);
            }
        }
    }

    int g = lane >> 2, t4 = lane & 3;
    #pragma unroll
    for (int mi = 0; mi < 2; mi++) {
        #pragma unroll
        for (int r = 0; r < 2; r++) {
            int row = wm + mi * 16 + g + r * 8;
            float inv = 1.f / rowsum[b * MPAD + m0 + row];
            float* hrow = Hp + ((long)b * MPAD + m0 + row) * DIM;
            #pragma unroll
            for (int nj = 0; nj < 8; nj++) {
                int col = wd + nj * 8 + t4 * 2;
                *(float2*)(hrow + col) =
                    make_float2(acc[mi][nj][r * 2 + 0] * inv,
                                acc[mi][nj][r * 2 + 1] * inv);
            }
        }
    }
}

// ---------------- norms + H sum: H0 = H0+H1 ; sw = ||H||/tau ----------------
__global__ __launch_bounds__(256)
void norms_kernel(float* __restrict__ H0, const float* __restrict__ H1,
                  const float* __restrict__ log_tau, float* __restrict__ sw)
{
    int b = blockIdx.y;
    int m = blockIdx.x * 8 + (threadIdx.x >> 5);
    int l = threadIdx.x & 31;
    float tau = fminf(fmaxf(expf(log_tau[0]) + 0.1f, 0.1f), 2.0f);
    long base = ((long)b * MPAD + m) * DIM;
    float s = 0.f;
    #pragma unroll
    for (int i = 0; i < 8; i++) {
        int idx = l + 32 * i;
        float x = H0[base + idx] + H1[base + idx];
        H0[base + idx] = x;
        s += x * x;
    }
    #pragma unroll
    for (int o = 16; o > 0; o >>= 1) s += __shfl_xor_sync(0xffffffffu, s, o);
    if (l == 0) sw[b * M_TOT + m] = sqrtf(s) / tau;
}

// ---------------- per-batch tail ----------------
__device__ __forceinline__ float blk_sum(float v, float* red, int t)
{
    __syncthreads();
    red[t] = v; __syncthreads();
    for (int s = 128; s > 0; s >>= 1) { if (t < s) red[t] += red[t + s]; __syncthreads(); }
    float r = red[0]; __syncthreads();
    return r;
}
__device__ __forceinline__ float blk_max(float v, float* red, int t)
{
    __syncthreads();
    red[t] = v; __syncthreads();
    for (int s = 128; s > 0; s >>= 1) { if (t < s) red[t] = fmaxf(red[t], red[t + s]); __syncthreads(); }
    float r = red[0]; __syncthreads();
    return r;
}
__device__ void softmax_sparsify(float* a, int len, float thr, float* red, int t)
{
    float m = -1e30f;
    for (int i = t; i < len; i += 256) m = fmaxf(m, a[i]);
    m = blk_max(m, red, t);
    float s = 0.f;
    for (int i = t; i < len; i += 256) { float e = expf(a[i] - m); a[i] = e; s += e; }
    s = blk_sum(s, red, t);
    float inv = 1.f / s;
    float s2 = 0.f;
    for (int i = t; i < len; i += 256) { float p = a[i] * inv; p = (p > thr) ? p : 0.f; a[i] = p; s2 += p; }
    s2 = blk_sum(s2, red, t);
    float inv2 = 1.f / (s2 + 1e-8f);
    for (int i = t; i < len; i += 256) a[i] *= inv2;
    __syncthreads();
}

__global__ __launch_bounds__(256)
void final_kernel(const float* __restrict__ H, const float* __restrict__ swg,
                  const float* __restrict__ part,
                  const float* __restrict__ cnt,
                  const float* __restrict__ Wg1, const float* __restrict__ bg1,
                  const float* __restrict__ Wg2, const float* __restrict__ bg2,
                  const float* __restrict__ Wo,  const float* __restrict__ bo,
                  const float* __restrict__ ln_g, const float* __restrict__ ln_b,
                  const float* __restrict__ lvlw, float* __restrict__ out)
{
    __shared__ float red[256];
    __shared__ float wcs[16], wts[128], wvs[512], wss[16];
    __shared__ float coeff[M_TOT];
    __shared__ float xc[512];
    __shared__ float hb[256], gb[256], yb[256], zg[256];
    __shared__ float lw[4];

    int b = blockIdx.x;
    int t = threadIdx.x;
    const float* Hb = H + (long)b * MPAD * DIM;
    const float* sw = swg + b * M_TOT;

    if (t == 0) {
        float m = fmaxf(fmaxf(lvlw[0], lvlw[1]), fmaxf(lvlw[2], lvlw[3]));
        float e0 = expf(lvlw[0]-m), e1 = expf(lvlw[1]-m), e2 = expf(lvlw[2]-m), e3 = expf(lvlw[3]-m);
        float s = e0+e1+e2+e3;
        lw[0]=e0/s; lw[1]=e1/s; lw[2]=e2/s; lw[3]=e3/s;
    }

    if (t < 16) wcs[t] = sw[t];
    __syncthreads();
    softmax_sparsify(wcs, 16, 0.1f, red, t);
    if (t < 128) wts[t] = sw[16 + t] * wcs[t >> 3];
    __syncthreads();
    softmax_sparsify(wts, 128, 0.05f, red, t);
    for (int i = t; i < 512; i += 256) wvs[i] = sw[144 + i] * wts[i >> 2];
    __syncthreads();
    softmax_sparsify(wvs, 512, 0.025f, red, t);
    if (t < 16) wss[t] = sw[656 + t];
    __syncthreads();
    softmax_sparsify(wss, 16, 0.1f, red, t);

    for (int i = t; i < M_TOT; i += 256) {
        float c;
        if (i < 16)       c = lw[0] * wcs[i];
        else if (i < 144) c = lw[1] * wts[i - 16];
        else if (i < 656) c = lw[2] * wvs[i - 144];
        else              c = lw[3] * wss[i - 656];
        coeff[i] = c;
    }
    __syncthreads();

    {
        float z0 = 0.f, z1 = 0.f, z2 = 0.f, z3 = 0.f;
        float z4 = 0.f, z5 = 0.f, z6 = 0.f, z7 = 0.f;
        #pragma unroll 2
        for (int m = 0; m < M_TOT; m += 8) {
            z0 += coeff[m]     * Hb[(m)     * DIM + t];
            z1 += coeff[m + 1] * Hb[(m + 1) * DIM + t];
            z2 += coeff[m + 2] * Hb[(m + 2) * DIM + t];
            z3 += coeff[m + 3] * Hb[(m + 3) * DIM + t];
            z4 += coeff[m + 4] * Hb[(m + 4) * DIM + t];
            z5 += coeff[m + 5] * Hb[(m + 5) * DIM + t];
            z6 += coeff[m + 6] * Hb[(m + 6) * DIM + t];
            z7 += coeff[m + 7] * Hb[(m + 7) * DIM + t];
        }
        xc[t] = ((z0 + z1) + (z2 + z3)) + ((z4 + z5) + (z6 + z7));
    }

    float pp = 0.f, cc = 0.f;
    #pragma unroll
    for (int s = 0; s < 16; s++) {
        pp += part[((long)b * 16 + s) * DIM + t];
        cc += cnt[b * 16 + s];
    }
    xc[256 + t] = pp / (cc + 1e-8f);
    __syncthreads();

    int w = t >> 5, l = t & 31;
    for (int j = w; j < 256; j += 8) {
        const float* wr = Wg1 + j * 512;
        float s = 0.f;
        #pragma unroll
        for (int i = 0; i < 16; i++) s += wr[l + 32 * i] * xc[l + 32 * i];
        #pragma unroll
        for (int o = 16; o > 0; o >>= 1) s += __shfl_xor_sync(0xffffffffu, s, o);
        if (l == 0) {
            float x = s + bg1[j];
            hb[j] = 0.5f * x * (1.0f + erff(x * 0.70710678118654752f));
        }
    }
    __syncthreads();

    for (int j = w; j < 256; j += 8) {
        const float* wr = Wg2 + j * 256;
        float s = 0.f;
        #pragma unroll
        for (int i = 0; i < 8; i++) s += wr[l + 32 * i] * hb[l + 32 * i];
        #pragma unroll
        for (int o = 16; o > 0; o >>= 1) s += __shfl_xor_sync(0xffffffffu, s, o);
        if (l == 0) gb[j] = 1.0f / (1.0f + expf(-(s + bg2[j])));
    }
    __syncthreads();

    zg[t] = xc[t] * gb[t];
    __syncthreads();

    for (int j = w; j < 256; j += 8) {
        const float* wr = Wo + j * 256;
        float s = 0.f;
        #pragma unroll
        for (int i = 0; i < 8; i++) s += wr[l + 32 * i] * zg[l + 32 * i];
        #pragma unroll
        for (int o = 16; o > 0; o >>= 1) s += __shfl_xor_sync(0xffffffffu, s, o);
        if (l == 0) yb[j] = s + bo[j];
    }
    __syncthreads();

    float y = yb[t];
    float mu = blk_sum(y, red, t) * (1.0f / 256.0f);
    float d0 = y - mu;
    float var = blk_sum(d0 * d0, red, t) * (1.0f / 256.0f);
    out[(long)b * DIM + t] = d0 * rsqrtf(var + 1e-5f) * ln_g[t] + ln_b[t];
}

// ---------------- masked position pooling partials ----------------
__global__ __launch_bounds__(256)
void pospool_partial(const float* __restrict__ pos, const unsigned char* __restrict__ mask,
                     float* __restrict__ part, float* __restrict__ cnt)
{
    int s = blockIdx.x, b = blockIdx.y;
    int t = threadIdx.x;
    const float* P = pos + ((long)b * NTOK + s * 256) * DIM;
    const unsigned char* M = mask + (long)b * NTOK + s * 256;
    float acc = 0.f, c = 0.f;
    for (int n = 0; n < 256; n++) {
        float mm = M[n] ? 1.f : 0.f;
        c += mm;
        acc += mm * P[(long)n * DIM + t];
    }
    part[((long)b * 16 + s) * DIM + t] = acc;
    if (t == 0) cnt[b * 16 + s] = c;
}

// ---------------- launch ----------------
extern "C" void kernel_launch(void* const* d_in, const int* in_sizes, int n_in,
                              void* d_out, int out_size)
{
    const float* X    = (const float*)d_in[0];
    const float* pos  = (const float*)d_in[1];
    const unsigned char* mask = (const unsigned char*)d_in[2];
    const float* cat  = (const float*)d_in[3];
    const float* typ  = (const float*)d_in[4];
    const float* var  = (const float*)d_in[5];
    const float* sp   = (const float*)d_in[6];
    const float* log_tau = (const float*)d_in[7];
    const float* Wk   = (const float*)d_in[8];
    const float* bk   = (const float*)d_in[9];
    const float* Wcat = (const float*)d_in[10];
    const float* bcat = (const float*)d_in[11];
    const float* Wtype= (const float*)d_in[12];
    const float* btype= (const float*)d_in[13];
    const float* Wvar = (const float*)d_in[14];
    const float* bvar = (const float*)d_in[15];
    const float* Wsp  = (const float*)d_in[16];
    const float* bsp  = (const float*)d_in[17];
    const float* Wg1  = (const float*)d_in[18];
    const float* bg1  = (const float*)d_in[19];
    const float* Wg2  = (const float*)d_in[20];
    const float* bg2  = (const float*)d_in[21];
    const float* Wo   = (const float*)d_in[22];
    const float* bo   = (const float*)d_in[23];
    const float* ln_g = (const float*)d_in[24];
    const float* ln_b = (const float*)d_in[25];
    const float* lvlw = (const float*)d_in[26];
    float* out = (float*)d_out;

    __half *Qh, *E, *Xh, *Xl;
    float *cvec, *rs, *H0, *H1, *sw, *part, *cnt;
    cudaGetSymbolAddress((void**)&Qh,   g_Qh);
    cudaGetSymbolAddress((void**)&cvec, g_c);
    cudaGetSymbolAddress((void**)&E,    g_E);
    cudaGetSymbolAddress((void**)&Xh,   g_Xh);
    cudaGetSymbolAddress((void**)&Xl,   g_Xl);
    cudaGetSymbolAddress((void**)&rs,   g_rs);
    cudaGetSymbolAddress((void**)&H0,   g_H0);
    cudaGetSymbolAddress((void**)&H1,   g_H1);
    cudaGetSymbolAddress((void**)&sw,   g_sw);
    cudaGetSymbolAddress((void**)&part, g_part);
    cudaGetSymbolAddress((void**)&cnt,  g_cnt);

    cudaFuncSetAttribute(logits_mma, cudaFuncAttributeMaxDynamicSharedMemorySize, 61568);
    cudaFuncSetAttribute(h_mma,      cudaFuncAttributeMaxDynamicSharedMemorySize, 77824);

    // 1) X -> fp16 hi/lo
    {
        long n4 = (long)BATCH * NTOK * DIM / 4;
        convert_x<<<(unsigned)(n4 / 256), 256>>>((const float4*)X,
                                                 (__half2*)Xh, (__half2*)Xl);
    }

    // 2) Q' and c ; zero rowsums
    prep_q<<<M_TOT, 256>>>(cat, typ, var, sp, Wcat, bcat, Wtype, btype,
                           Wvar, bvar, Wsp, bsp, Wk, bk, Qh, cvec);
    rs_zero<<<(BATCH * MPAD) / 256, 256>>>(rs);

    // 3) logits -> exp (fp16) + row sums
    {
        dim3 grid(NTOK / 128, MPAD / 128, BATCH);
        logits_mma<<<grid, 256, 61568>>>(Qh, Xh, E, rs, cvec, mask);
    }

    // 4) H partials = (E @ X) / rowsum, K split in 2
    {
        dim3 grid(2, 11, BATCH);
        h_mma<<<grid, 256, 77824>>>(E, Xh, Xl, rs, H0, H1);
    }

    // 5) position pooling partials
    {
        dim3 grid(16, BATCH);
        pospool_partial<<<grid, 256>>>(pos, mask, part, cnt);
    }

    // 6) norms + H sum
    {
        dim3 grid(M_TOT / 8, BATCH);
        norms_kernel<<<grid, 256>>>(H0, H1, log_tau, sw);
    }

    // 7) per-batch tail
    final_kernel<<<BATCH, 256>>>(H0, sw, part, cnt,
                                 Wg1, bg1, Wg2, bg2, Wo, bo,
                                 ln_g, ln_b, lvlw, out);
}

// round 13
// speedup vs baseline: 1.0818x; 1.0818x over previous
#include <cuda_runtime.h>
#include <cuda_bf16.h>
#include <cuda_fp16.h>
#include <math.h>

#define BATCH 32
#define NTOK  4096
#define DIM   256
#define M_TOT 672
#define MPAD  768

// ---------------- scratch ----------------
__device__ __half g_Qh[MPAD * DIM];          // Q' * 64
__device__ float  g_c [MPAD];
__device__ __half g_E [(long)BATCH * MPAD * NTOK];
__device__ __half g_Xh[(long)BATCH * NTOK * DIM];
__device__ __half g_Xl[(long)BATCH * NTOK * DIM];
__device__ float g_rs[BATCH * MPAD];
__device__ float g_H0[(long)BATCH * MPAD * DIM];
__device__ float g_H1[(long)BATCH * MPAD * DIM];
__device__ float g_sw[BATCH * M_TOT];
__device__ float g_part[BATCH * 16 * DIM];
__device__ float g_cnt [BATCH * 16];

// ---------------- helpers ----------------
__device__ __forceinline__ unsigned sm_u32(const void* p) {
    return (unsigned)__cvta_generic_to_shared(p);
}
__device__ __forceinline__ void cpa16(unsigned s, const void* g) {
    asm volatile("cp.async.cg.shared.global [%0], [%1], 16;" :: "r"(s), "l"(g));
}
__device__ __forceinline__ void cpa_commit() { asm volatile("cp.async.commit_group;"); }
template<int N> __device__ __forceinline__ void cpa_wait() {
    asm volatile("cp.async.wait_group %0;" :: "n"(N));
}
__device__ __forceinline__ void ldsm4(unsigned r[4], unsigned addr) {
    asm volatile("ldmatrix.sync.aligned.m8n8.x4.shared.b16 {%0,%1,%2,%3},[%4];"
                 : "=r"(r[0]), "=r"(r[1]), "=r"(r[2]), "=r"(r[3]) : "r"(addr));
}
__device__ __forceinline__ void ldsm2(unsigned r[2], unsigned addr) {
    asm volatile("ldmatrix.sync.aligned.m8n8.x2.shared.b16 {%0,%1},[%2];"
                 : "=r"(r[0]), "=r"(r[1]) : "r"(addr));
}
__device__ __forceinline__ void ldsm2t(unsigned r[2], unsigned addr) {
    asm volatile("ldmatrix.sync.aligned.m8n8.x2.trans.shared.b16 {%0,%1},[%2];"
                 : "=r"(r[0]), "=r"(r[1]) : "r"(addr));
}
__device__ __forceinline__ void mma16816(float c[4], const unsigned a[4], const unsigned b[2]) {
    asm volatile(
        "mma.sync.aligned.m16n8k16.row.col.f32.f16.f16.f32 "
        "{%0,%1,%2,%3},{%4,%5,%6,%7},{%8,%9},{%0,%1,%2,%3};"
        : "+f"(c[0]), "+f"(c[1]), "+f"(c[2]), "+f"(c[3])
        : "r"(a[0]), "r"(a[1]), "r"(a[2]), "r"(a[3]), "r"(b[0]), "r"(b[1]));
}

// ---------------- zero rowsums ----------------
__global__ __launch_bounds__(256)
void rs_zero(float* __restrict__ rs)
{
    rs[blockIdx.x * 256 + threadIdx.x] = 0.f;
}

// ---------------- X -> fp16 hi/lo ----------------
__global__ __launch_bounds__(256)
void convert_x(const float4* __restrict__ X, __half2* __restrict__ Xh,
               __half2* __restrict__ Xl)
{
    long i = (long)blockIdx.x * 256 + threadIdx.x;
    float4 v = X[i];
    __half hx = __float2half(v.x), hy = __float2half(v.y);
    __half hz = __float2half(v.z), hw = __float2half(v.w);
    Xh[i * 2]     = __halves2half2(hx, hy);
    Xh[i * 2 + 1] = __halves2half2(hz, hw);
    Xl[i * 2]     = __halves2half2(__float2half(v.x - __half2float(hx)),
                                   __float2half(v.y - __half2float(hy)));
    Xl[i * 2 + 1] = __halves2half2(__float2half(v.z - __half2float(hz)),
                                   __float2half(v.w - __half2float(hw)));
}

// ---------------- prep ----------------
__global__ __launch_bounds__(256)
void prep_q(const float* __restrict__ cat, const float* __restrict__ typ,
            const float* __restrict__ var, const float* __restrict__ sp,
            const float* __restrict__ Wcat, const float* __restrict__ bcat,
            const float* __restrict__ Wtype, const float* __restrict__ btype,
            const float* __restrict__ Wvar, const float* __restrict__ bvar,
            const float* __restrict__ Wsp, const float* __restrict__ bsp,
            const float* __restrict__ Wk, const float* __restrict__ bk,
            __half* __restrict__ Qh, float* __restrict__ cvec)
{
    int m = blockIdx.x;
    const float* codes; const float* Wq; const float* bq;
    if (m < 16)       { codes = cat + m * DIM;         Wq = Wcat;  bq = bcat; }
    else if (m < 144) { codes = typ + (m - 16) * DIM;  Wq = Wtype; bq = btype; }
    else if (m < 656) { codes = var + (m - 144) * DIM; Wq = Wvar;  bq = bvar; }
    else              { codes = sp + (m - 656) * DIM;  Wq = Wsp;   bq = bsp; }

    __shared__ float cs[DIM], qs[DIM], red[256];
    int t = threadIdx.x;
    cs[t] = codes[t];
    __syncthreads();

    int w = t >> 5, l = t & 31;
    for (int j = w; j < DIM; j += 8) {
        const float* wr = Wq + j * DIM;
        float s = 0.f;
        #pragma unroll
        for (int i = 0; i < 8; i++) s += wr[l + 32 * i] * cs[l + 32 * i];
        #pragma unroll
        for (int o = 16; o > 0; o >>= 1) s += __shfl_xor_sync(0xffffffffu, s, o);
        if (l == 0) qs[j] = s + bq[j];
    }
    __syncthreads();

    float a = 0.f;
    for (int j = 0; j < DIM; j++) a += qs[j] * Wk[j * DIM + t];
    Qh[m * DIM + t] = __float2half(a * 64.0f);

    red[t] = qs[t] * bk[t];
    __syncthreads();
    for (int s = 128; s > 0; s >>= 1) { if (t < s) red[t] += red[t + s]; __syncthreads(); }
    if (t == 0) cvec[m] = red[0] * 0.0625f;
}

// ---------------- logits+exp (2-stage pipeline, occupancy-pinned) ----------------
extern __shared__ char dsm[];

__global__ void __launch_bounds__(256, 2)
logits_mma(const __half* __restrict__ Qh,
           const __half* __restrict__ Xh,
           __half* __restrict__ E,
           float* __restrict__ rowsum,
           const float* __restrict__ cvec,
           const unsigned char* __restrict__ mask)
{
    const int SK = 40;
    const int STAGE = 20480;
    const int SE = 136;

    int b = blockIdx.z;
    int m0 = blockIdx.y * 128, n0 = blockIdx.x * 128;
    const __half* Xb = Xh + (long)b * NTOK * DIM;
    int t = threadIdx.x, lane = t & 31, w = t >> 5;
    int wm = (w >> 2) * 64, wn = (w & 3) * 32;
    int l15 = lane & 15, t4 = lane & 3;

    unsigned char* maskc = (unsigned char*)(dsm + 2 * STAGE);
    if (t < 128) maskc[t] = mask[(long)b * NTOK + n0 + t];

    auto load_stage = [&](int kt, int s) {
        char* base = dsm + s * STAGE;
        #pragma unroll
        for (int i = 0; i < 2; i++) {
            int c = t + i * 256;
            int row = c >> 2, kq = c & 3;
            cpa16(sm_u32(base + (row * SK + kq * 8) * 2),
                  Qh + (m0 + row) * DIM + kt * 32 + kq * 8);
            cpa16(sm_u32(base + 10240 + (row * SK + kq * 8) * 2),
                  Xb + (long)(n0 + row) * DIM + kt * 32 + kq * 8);
        }
        cpa_commit();
    };

    float acc[4][4][4] = {};
    load_stage(0, 0);
    for (int kt = 0; kt < 8; kt++) {
        cpa_wait<0>();
        __syncthreads();
        if (kt < 7) load_stage(kt + 1, (kt + 1) & 1);
        char* base = dsm + (kt & 1) * STAGE;
        unsigned aBase = sm_u32(base + ((wm + l15) * SK + (lane >> 4) * 8) * 2);
        unsigned bBase = sm_u32(base + 10240 + ((wn + (l15 & 7)) * SK + (l15 >> 3) * 8) * 2);
        #pragma unroll
        for (int ks = 0; ks < 2; ks++) {
            unsigned a[4][4], bf[4][2];
            #pragma unroll
            for (int mi = 0; mi < 4; mi++) ldsm4(a[mi], aBase + (unsigned)(mi * 16 * SK + ks * 16) * 2u);
            #pragma unroll
            for (int ni = 0; ni < 4; ni++) ldsm2(bf[ni], bBase + (unsigned)(ni * 8 * SK + ks * 16) * 2u);
            #pragma unroll
            for (int mi = 0; mi < 4; mi++)
                #pragma unroll
                for (int ni = 0; ni < 4; ni++) mma16816(acc[mi][ni], a[mi], bf[ni]);
        }
    }
    __syncthreads();   // reuse stage smem for epilogue staging

    __half* sE = (__half*)dsm;
    const float DS = 1.0f / 1024.0f;

    #pragma unroll
    for (int mi = 0; mi < 4; mi++) {
        #pragma unroll
        for (int r = 0; r < 2; r++) {
            int row = wm + mi * 16 + (lane >> 2) + r * 8;
            float cv = cvec[m0 + row];
            float rs = 0.f;
            #pragma unroll
            for (int ni = 0; ni < 4; ni++) {
                int col = wn + ni * 8 + t4 * 2;
                float x0 = acc[mi][ni][r * 2 + 0] * DS + cv;
                float x1 = acc[mi][ni][r * 2 + 1] * DS + cv;
                x0 = fminf(fmaxf(x0, -50.f), 50.f);
                x1 = fminf(fmaxf(x1, -50.f), 50.f);
                if (!maskc[col])     x0 = -50.f;
                if (!maskc[col + 1]) x1 = -50.f;
                float e0 = __expf(x0);
                float e1 = __expf(x1);
                rs += e0 + e1;
                *(__half2*)(sE + row * SE + col) =
                    __halves2half2(__float2half(e0), __float2half(e1));
            }
            rs += __shfl_xor_sync(0xffffffffu, rs, 1);
            rs += __shfl_xor_sync(0xffffffffu, rs, 2);
            if (t4 == 0) atomicAdd(&rowsum[b * MPAD + m0 + row], rs);
        }
    }
    __syncthreads();

    long robase = ((long)b * MPAD + m0) * NTOK + n0;
    #pragma unroll
    for (int i = 0; i < 8; i++) {
        int c = t + i * 256;
        int row = c >> 4, seg = c & 15;
        uint4 vh = *(uint4*)(sE + row * SE + seg * 8);
        *(uint4*)(E + robase + (long)row * NTOK + seg * 8) = vh;
    }
}

// ---------------- H partials: Hp = (E @ X) / rowsum over a K split ----------------
__global__ __launch_bounds__(256)
void h_mma(const __half* __restrict__ E,
           const __half* __restrict__ Xh, const __half* __restrict__ Xl,
           const float* __restrict__ rowsum,
           float* __restrict__ H0, float* __restrict__ H1)
{
    const int SK = 40, SN = 264;
    const int STAGE = 38912;

    int b = blockIdx.z;
    int split = blockIdx.x;              // 0 or 1
    int k0 = split * 64;                 // of 128 K-chunks
    int m0 = blockIdx.y * 64;
    float* Hp = split ? H1 : H0;
    const __half* Eb  = E  + ((long)b * MPAD + m0) * NTOK;
    const __half* Xhb = Xh + (long)b * NTOK * DIM;
    const __half* Xlb = Xl + (long)b * NTOK * DIM;
    int t = threadIdx.x, lane = t & 31, w = t >> 5;
    int wm = (w >> 2) * 32, wd = (w & 3) * 64;
    int l15 = lane & 15;

    auto load_stage = [&](int kt, int s) {
        char* base = dsm + s * STAGE;
        {
            int row = t >> 2, kq = t & 3;
            long off = (long)row * NTOK + kt * 32 + kq * 8;
            cpa16(sm_u32(base + (row * SK + kq * 8) * 2), Eb + off);
        }
        #pragma unroll
        for (int i = 0; i < 4; i++) {
            int c = t + i * 256;
            int kr = c >> 5, nc = (c & 31) * 8;
            long off = (long)(kt * 32 + kr) * DIM + nc;
            cpa16(sm_u32(base + 5120 + (kr * SN + nc) * 2), Xhb + off);
            cpa16(sm_u32(base + 22016 + (kr * SN + nc) * 2), Xlb + off);
        }
        cpa_commit();
    };

    float acc[2][8][4] = {};
    load_stage(k0, 0);
    for (int i = 0; i < 64; i++) {
        int kt = k0 + i;
        cpa_wait<0>();
        __syncthreads();
        if (i < 63) load_stage(kt + 1, (i + 1) & 1);
        char* base = dsm + (i & 1) * STAGE;
        unsigned aB  = sm_u32(base + ((wm + l15) * SK + (lane >> 4) * 8) * 2);
        unsigned bhB = sm_u32(base + 5120 + (l15 * SN + wd) * 2);
        unsigned blB = bhB + (22016 - 5120);
        #pragma unroll
        for (int ks = 0; ks < 2; ks++) {
            unsigned a[2][4];
            ldsm4(a[0], aB + (unsigned)(0 * 16 * SK + ks * 16) * 2u);
            ldsm4(a[1], aB + (unsigned)(1 * 16 * SK + ks * 16) * 2u);
            #pragma unroll
            for (int nj = 0; nj < 8; nj++) {
                unsigned bh[2], bl[2];
                ldsm2t(bh, bhB + (unsigned)(ks * 16 * SN) * 2u + (unsigned)nj * 16u);
                ldsm2t(bl, blB + (unsigned)(ks * 16 * SN) * 2u + (unsigned)nj * 16u);
                mma16816(acc[0][nj], a[0], bh);
                mma16816(acc[1][nj], a[1], bh);
                mma16816(acc[0][nj], a[0], bl);
                mma16816(acc[1][nj], a[1], bl);
            }
        }
    }

    int g = lane >> 2, t4 = lane & 3;
    #pragma unroll
    for (int mi = 0; mi < 2; mi++) {
        #pragma unroll
        for (int r = 0; r < 2; r++) {
            int row = wm + mi * 16 + g + r * 8;
            float inv = 1.f / rowsum[b * MPAD + m0 + row];
            float* hrow = Hp + ((long)b * MPAD + m0 + row) * DIM;
            #pragma unroll
            for (int nj = 0; nj < 8; nj++) {
                int col = wd + nj * 8 + t4 * 2;
                *(float2*)(hrow + col) =
                    make_float2(acc[mi][nj][r * 2 + 0] * inv,
                                acc[mi][nj][r * 2 + 1] * inv);
            }
        }
    }
}

// ---------------- norms + H sum: H0 = H0+H1 ; sw = ||H||/tau ----------------
__global__ __launch_bounds__(256)
void norms_kernel(float* __restrict__ H0, const float* __restrict__ H1,
                  const float* __restrict__ log_tau, float* __restrict__ sw)
{
    int b = blockIdx.y;
    int m = blockIdx.x * 8 + (threadIdx.x >> 5);
    int l = threadIdx.x & 31;
    float tau = fminf(fmaxf(expf(log_tau[0]) + 0.1f, 0.1f), 2.0f);
    long base = ((long)b * MPAD + m) * DIM;
    float s = 0.f;
    #pragma unroll
    for (int i = 0; i < 8; i++) {
        int idx = l + 32 * i;
        float x = H0[base + idx] + H1[base + idx];
        H0[base + idx] = x;
        s += x * x;
    }
    #pragma unroll
    for (int o = 16; o > 0; o >>= 1) s += __shfl_xor_sync(0xffffffffu, s, o);
    if (l == 0) sw[b * M_TOT + m] = sqrtf(s) / tau;
}

// ---------------- per-batch tail ----------------
__device__ __forceinline__ float blk_sum(float v, float* red, int t)
{
    __syncthreads();
    red[t] = v; __syncthreads();
    for (int s = 128; s > 0; s >>= 1) { if (t < s) red[t] += red[t + s]; __syncthreads(); }
    float r = red[0]; __syncthreads();
    return r;
}
__device__ __forceinline__ float blk_max(float v, float* red, int t)
{
    __syncthreads();
    red[t] = v; __syncthreads();
    for (int s = 128; s > 0; s >>= 1) { if (t < s) red[t] = fmaxf(red[t], red[t + s]); __syncthreads(); }
    float r = red[0]; __syncthreads();
    return r;
}
__device__ void softmax_sparsify(float* a, int len, float thr, float* red, int t)
{
    float m = -1e30f;
    for (int i = t; i < len; i += 256) m = fmaxf(m, a[i]);
    m = blk_max(m, red, t);
    float s = 0.f;
    for (int i = t; i < len; i += 256) { float e = expf(a[i] - m); a[i] = e; s += e; }
    s = blk_sum(s, red, t);
    float inv = 1.f / s;
    float s2 = 0.f;
    for (int i = t; i < len; i += 256) { float p = a[i] * inv; p = (p > thr) ? p : 0.f; a[i] = p; s2 += p; }
    s2 = blk_sum(s2, red, t);
    float inv2 = 1.f / (s2 + 1e-8f);
    for (int i = t; i < len; i += 256) a[i] *= inv2;
    __syncthreads();
}

__global__ __launch_bounds__(256)
void final_kernel(const float* __restrict__ H, const float* __restrict__ swg,
                  const float* __restrict__ part,
                  const float* __restrict__ cnt,
                  const float* __restrict__ Wg1, const float* __restrict__ bg1,
                  const float* __restrict__ Wg2, const float* __restrict__ bg2,
                  const float* __restrict__ Wo,  const float* __restrict__ bo,
                  const float* __restrict__ ln_g, const float* __restrict__ ln_b,
                  const float* __restrict__ lvlw, float* __restrict__ out)
{
    __shared__ float red[256];
    __shared__ float wcs[16], wts[128], wvs[512], wss[16];
    __shared__ float coeff[M_TOT];
    __shared__ float xc[512];
    __shared__ float hb[256], gb[256], yb[256], zg[256];
    __shared__ float lw[4];

    int b = blockIdx.x;
    int t = threadIdx.x;
    const float* Hb = H + (long)b * MPAD * DIM;
    const float* sw = swg + b * M_TOT;

    if (t == 0) {
        float m = fmaxf(fmaxf(lvlw[0], lvlw[1]), fmaxf(lvlw[2], lvlw[3]));
        float e0 = expf(lvlw[0]-m), e1 = expf(lvlw[1]-m), e2 = expf(lvlw[2]-m), e3 = expf(lvlw[3]-m);
        float s = e0+e1+e2+e3;
        lw[0]=e0/s; lw[1]=e1/s; lw[2]=e2/s; lw[3]=e3/s;
    }

    if (t < 16) wcs[t] = sw[t];
    __syncthreads();
    softmax_sparsify(wcs, 16, 0.1f, red, t);
    if (t < 128) wts[t] = sw[16 + t] * wcs[t >> 3];
    __syncthreads();
    softmax_sparsify(wts, 128, 0.05f, red, t);
    for (int i = t; i < 512; i += 256) wvs[i] = sw[144 + i] * wts[i >> 2];
    __syncthreads();
    softmax_sparsify(wvs, 512, 0.025f, red, t);
    if (t < 16) wss[t] = sw[656 + t];
    __syncthreads();
    softmax_sparsify(wss, 16, 0.1f, red, t);

    for (int i = t; i < M_TOT; i += 256) {
        float c;
        if (i < 16)       c = lw[0] * wcs[i];
        else if (i < 144) c = lw[1] * wts[i - 16];
        else if (i < 656) c = lw[2] * wvs[i - 144];
        else              c = lw[3] * wss[i - 656];
        coeff[i] = c;
    }
    __syncthreads();

    {
        float z0 = 0.f, z1 = 0.f, z2 = 0.f, z3 = 0.f;
        float z4 = 0.f, z5 = 0.f, z6 = 0.f, z7 = 0.f;
        #pragma unroll 2
        for (int m = 0; m < M_TOT; m += 8) {
            z0 += coeff[m]     * Hb[(m)     * DIM + t];
            z1 += coeff[m + 1] * Hb[(m + 1) * DIM + t];
            z2 += coeff[m + 2] * Hb[(m + 2) * DIM + t];
            z3 += coeff[m + 3] * Hb[(m + 3) * DIM + t];
            z4 += coeff[m + 4] * Hb[(m + 4) * DIM + t];
            z5 += coeff[m + 5] * Hb[(m + 5) * DIM + t];
            z6 += coeff[m + 6] * Hb[(m + 6) * DIM + t];
            z7 += coeff[m + 7] * Hb[(m + 7) * DIM + t];
        }
        xc[t] = ((z0 + z1) + (z2 + z3)) + ((z4 + z5) + (z6 + z7));
    }

    float pp = 0.f, cc = 0.f;
    #pragma unroll
    for (int s = 0; s < 16; s++) {
        pp += part[((long)b * 16 + s) * DIM + t];
        cc += cnt[b * 16 + s];
    }
    xc[256 + t] = pp / (cc + 1e-8f);
    __syncthreads();

    int w = t >> 5, l = t & 31;
    for (int j = w; j < 256; j += 8) {
        const float* wr = Wg1 + j * 512;
        float s = 0.f;
        #pragma unroll
        for (int i = 0; i < 16; i++) s += wr[l + 32 * i] * xc[l + 32 * i];
        #pragma unroll
        for (int o = 16; o > 0; o >>= 1) s += __shfl_xor_sync(0xffffffffu, s, o);
        if (l == 0) {
            float x = s + bg1[j];
            hb[j] = 0.5f * x * (1.0f + erff(x * 0.70710678118654752f));
        }
    }
    __syncthreads();

    for (int j = w; j < 256; j += 8) {
        const float* wr = Wg2 + j * 256;
        float s = 0.f;
        #pragma unroll
        for (int i = 0; i < 8; i++) s += wr[l + 32 * i] * hb[l + 32 * i];
        #pragma unroll
        for (int o = 16; o > 0; o >>= 1) s += __shfl_xor_sync(0xffffffffu, s, o);
        if (l == 0) gb[j] = 1.0f / (1.0f + expf(-(s + bg2[j])));
    }
    __syncthreads();

    zg[t] = xc[t] * gb[t];
    __syncthreads();

    for (int j = w; j < 256; j += 8) {
        const float* wr = Wo + j * 256;
        float s = 0.f;
        #pragma unroll
        for (int i = 0; i < 8; i++) s += wr[l + 32 * i] * zg[l + 32 * i];
        #pragma unroll
        for (int o = 16; o > 0; o >>= 1) s += __shfl_xor_sync(0xffffffffu, s, o);
        if (l == 0) yb[j] = s + bo[j];
    }
    __syncthreads();

    float y = yb[t];
    float mu = blk_sum(y, red, t) * (1.0f / 256.0f);
    float d0 = y - mu;
    float var = blk_sum(d0 * d0, red, t) * (1.0f / 256.0f);
    out[(long)b * DIM + t] = d0 * rsqrtf(var + 1e-5f) * ln_g[t] + ln_b[t];
}

// ---------------- masked position pooling partials ----------------
__global__ __launch_bounds__(256)
void pospool_partial(const float* __restrict__ pos, const unsigned char* __restrict__ mask,
                     float* __restrict__ part, float* __restrict__ cnt)
{
    int s = blockIdx.x, b = blockIdx.y;
    int t = threadIdx.x;
    const float* P = pos + ((long)b * NTOK + s * 256) * DIM;
    const unsigned char* M = mask + (long)b * NTOK + s * 256;
    float acc = 0.f, c = 0.f;
    for (int n = 0; n < 256; n++) {
        float mm = M[n] ? 1.f : 0.f;
        c += mm;
        acc += mm * P[(long)n * DIM + t];
    }
    part[((long)b * 16 + s) * DIM + t] = acc;
    if (t == 0) cnt[b * 16 + s] = c;
}

// ---------------- launch ----------------
extern "C" void kernel_launch(void* const* d_in, const int* in_sizes, int n_in,
                              void* d_out, int out_size)
{
    const float* X    = (const float*)d_in[0];
    const float* pos  = (const float*)d_in[1];
    const unsigned char* mask = (const unsigned char*)d_in[2];
    const float* cat  = (const float*)d_in[3];
    const float* typ  = (const float*)d_in[4];
    const float* var  = (const float*)d_in[5];
    const float* sp   = (const float*)d_in[6];
    const float* log_tau = (const float*)d_in[7];
    const float* Wk   = (const float*)d_in[8];
    const float* bk   = (const float*)d_in[9];
    const float* Wcat = (const float*)d_in[10];
    const float* bcat = (const float*)d_in[11];
    const float* Wtype= (const float*)d_in[12];
    const float* btype= (const float*)d_in[13];
    const float* Wvar = (const float*)d_in[14];
    const float* bvar = (const float*)d_in[15];
    const float* Wsp  = (const float*)d_in[16];
    const float* bsp  = (const float*)d_in[17];
    const float* Wg1  = (const float*)d_in[18];
    const float* bg1  = (const float*)d_in[19];
    const float* Wg2  = (const float*)d_in[20];
    const float* bg2  = (const float*)d_in[21];
    const float* Wo   = (const float*)d_in[22];
    const float* bo   = (const float*)d_in[23];
    const float* ln_g = (const float*)d_in[24];
    const float* ln_b = (const float*)d_in[25];
    const float* lvlw = (const float*)d_in[26];
    float* out = (float*)d_out;

    __half *Qh, *E, *Xh, *Xl;
    float *cvec, *rs, *H0, *H1, *sw, *part, *cnt;
    cudaGetSymbolAddress((void**)&Qh,   g_Qh);
    cudaGetSymbolAddress((void**)&cvec, g_c);
    cudaGetSymbolAddress((void**)&E,    g_E);
    cudaGetSymbolAddress((void**)&Xh,   g_Xh);
    cudaGetSymbolAddress((void**)&Xl,   g_Xl);
    cudaGetSymbolAddress((void**)&rs,   g_rs);
    cudaGetSymbolAddress((void**)&H0,   g_H0);
    cudaGetSymbolAddress((void**)&H1,   g_H1);
    cudaGetSymbolAddress((void**)&sw,   g_sw);
    cudaGetSymbolAddress((void**)&part, g_part);
    cudaGetSymbolAddress((void**)&cnt,  g_cnt);

    cudaFuncSetAttribute(logits_mma, cudaFuncAttributeMaxDynamicSharedMemorySize, 41088);
    cudaFuncSetAttribute(h_mma,      cudaFuncAttributeMaxDynamicSharedMemorySize, 77824);

    // 1) X -> fp16 hi/lo
    {
        long n4 = (long)BATCH * NTOK * DIM / 4;
        convert_x<<<(unsigned)(n4 / 256), 256>>>((const float4*)X,
                                                 (__half2*)Xh, (__half2*)Xl);
    }

    // 2) Q' and c ; zero rowsums
    prep_q<<<M_TOT, 256>>>(cat, typ, var, sp, Wcat, bcat, Wtype, btype,
                           Wvar, bvar, Wsp, bsp, Wk, bk, Qh, cvec);
    rs_zero<<<(BATCH * MPAD) / 256, 256>>>(rs);

    // 3) logits -> exp (fp16) + row sums
    {
        dim3 grid(NTOK / 128, MPAD / 128, BATCH);
        logits_mma<<<grid, 256, 41088>>>(Qh, Xh, E, rs, cvec, mask);
    }

    // 4) H partials = (E @ X) / rowsum, K split in 2
    {
        dim3 grid(2, 11, BATCH);
        h_mma<<<grid, 256, 77824>>>(E, Xh, Xl, rs, H0, H1);
    }

    // 5) position pooling partials
    {
        dim3 grid(16, BATCH);
        pospool_partial<<<grid, 256>>>(pos, mask, part, cnt);
    }

    // 6) norms + H sum
    {
        dim3 grid(M_TOT / 8, BATCH);
        norms_kernel<<<grid, 256>>>(H0, H1, log_tau, sw);
    }

    // 7) per-batch tail
    final_kernel<<<BATCH, 256>>>(H0, sw, part, cnt,
                                 Wg1, bg1, Wg2, bg2, Wo, bo,
                                 ln_g, ln_b, lvlw, out);
}